// round 8
// baseline (speedup 1.0000x reference)
#include <cuda_runtime.h>
#include <cuda_bf16.h>
#include <stdint.h>
#include <math.h>

#define EPSF 1e-8f
#define NMAX 50000
#define D1 128
#define D2 256
#define BF16_MARGIN 0.02f

// ---------------------------------------------------------------------------
// Scratch (device globals — no allocation allowed).
// ---------------------------------------------------------------------------
__device__ float4 g_agg1_[(size_t)NMAX * D1 / 4];
__device__ float4 g_h_[(size_t)NMAX * D2 / 4];
__device__ float4 g_agg2_[(size_t)NMAX * D2 / 4];
__device__ uint4  g_xb_[(size_t)NMAX * D1 / 8];
__device__ uint4  g_hb_[(size_t)NMAX * D2 / 8];
__device__ float  g_xnorm[NMAX];
__device__ float  g_hnorm[NMAX];
__device__ unsigned g_w1hi[256 * 128 / 2];
__device__ unsigned g_w1lo[256 * 128 / 2];
__device__ unsigned g_w2hi[64 * 256 / 2];
__device__ unsigned g_w2lo[64 * 256 / 2];
__device__ int    g_is64;

// ---------------------------------------------------------------------------
// helpers
// ---------------------------------------------------------------------------
__device__ __forceinline__ uint32_t smem_u32(const void* p) {
    uint32_t a;
    asm("{ .reg .u64 t; cvta.to.shared.u64 t, %1; cvt.u32.u64 %0, t; }"
        : "=r"(a) : "l"(p));
    return a;
}
__device__ __forceinline__ void ldsm_x4(uint32_t a[4], uint32_t addr) {
    asm volatile("ldmatrix.sync.aligned.m8n8.x4.shared.b16 {%0,%1,%2,%3}, [%4];"
        : "=r"(a[0]), "=r"(a[1]), "=r"(a[2]), "=r"(a[3]) : "r"(addr));
}
__device__ __forceinline__ void ldsm_x2(uint32_t a[2], uint32_t addr) {
    asm volatile("ldmatrix.sync.aligned.m8n8.x2.shared.b16 {%0,%1}, [%2];"
        : "=r"(a[0]), "=r"(a[1]) : "r"(addr));
}
__device__ __forceinline__ void mma_bf16(float c[4], const uint32_t a[4],
                                         const uint32_t b[2]) {
    asm volatile("mma.sync.aligned.m16n8k16.row.col.f32.bf16.bf16.f32 "
        "{%0,%1,%2,%3}, {%4,%5,%6,%7}, {%8,%9}, {%0,%1,%2,%3};"
        : "+f"(c[0]), "+f"(c[1]), "+f"(c[2]), "+f"(c[3])
        : "r"(a[0]), "r"(a[1]), "r"(a[2]), "r"(a[3]), "r"(b[0]), "r"(b[1]));
}
__device__ __forceinline__ unsigned pack2bf(float a, float b) {
    __nv_bfloat162 t = __floats2bfloat162_rn(a, b);
    return *(unsigned*)&t;
}
__device__ __forceinline__ void split2bf(float a, float b, unsigned& hi, unsigned& lo) {
    __nv_bfloat16 ha = __float2bfloat16_rn(a), hb = __float2bfloat16_rn(b);
    float ra = a - __bfloat162float(ha), rb = b - __bfloat162float(hb);
    __nv_bfloat162 hp;
    hp.x = ha; hp.y = hb;
    hi = *(unsigned*)&hp;
    lo = pack2bf(ra, rb);
}
__device__ __forceinline__ uint2 pack_bf16x4(float4 v) {
    uint2 r;
    r.x = pack2bf(v.x, v.y);
    r.y = pack2bf(v.z, v.w);
    return r;
}

// ---------------------------------------------------------------------------
// small setup kernels
// ---------------------------------------------------------------------------
__global__ void k_init_flag() { g_is64 = 1; }

__global__ void k_detect64(const void* __restrict__ eidx, int E, int N) {
    int i = blockIdx.x * blockDim.x + threadIdx.x;
    if (i < E) {
        long long v = ((const long long*)eidx)[i];
        if (v < 0 || v >= (long long)N) g_is64 = 0;
    }
}

__global__ void k_wsplit(const float* __restrict__ w, unsigned* __restrict__ hi,
                         unsigned* __restrict__ lo, int n) {
    int i = blockIdx.x * blockDim.x + threadIdx.x;
    if (i < n) {
        float2 v = ((const float2*)w)[i];
        unsigned h, l;
        split2bf(v.x, v.y, h, l);
        hi[i] = h;
        lo[i] = l;
    }
}

// ---------------------------------------------------------------------------
// Per-node norms + self-loop init + bf16 conversion (layer-1 input x).
// ---------------------------------------------------------------------------
template<int D>
__global__ void k_norms_init(const float* __restrict__ feat,
                             float* __restrict__ norms,
                             float* __restrict__ agg,
                             uint2* __restrict__ fb, int N)
{
    int node = (blockIdx.x * blockDim.x + threadIdx.x) >> 5;
    int lane = threadIdx.x & 31;
    if (node >= N) return;
    const float4* f = (const float4*)(feat + (size_t)node * D);
    float4* a = (float4*)(agg + (size_t)node * D);
    uint2* fbr = fb + (size_t)node * (D / 4);
    float4 v[D / 128];
    float n2 = 0.f;
#pragma unroll
    for (int i = 0; i < D / 128; i++) {
        v[i] = f[lane + 32 * i];
        n2 += v[i].x * v[i].x + v[i].y * v[i].y + v[i].z * v[i].z + v[i].w * v[i].w;
    }
#pragma unroll
    for (int i = 0; i < D / 128; i++) fbr[lane + 32 * i] = pack_bf16x4(v[i]);
#pragma unroll
    for (int o = 16; o; o >>= 1) n2 += __shfl_xor_sync(0xffffffffu, n2, o);
    float nrm = sqrtf(n2);
    if (lane == 0) norms[node] = nrm;
    float denom = fmaxf(nrm * nrm, EPSF);
    bool pass = n2 > 0.5f * denom;
    float4 z = make_float4(0.f, 0.f, 0.f, 0.f);
#pragma unroll
    for (int i = 0; i < D / 128; i++) a[lane + 32 * i] = pass ? v[i] : z;
}

// ---------------------------------------------------------------------------
// Edge pass, half-warp per edge (unchanged from R5).
// ---------------------------------------------------------------------------
template<int D, int U4>
__global__ void k_edge_half(const float* __restrict__ feat,
                            const uint4* __restrict__ fb,
                            const float* __restrict__ norms,
                            const void* __restrict__ eidx,
                            float* __restrict__ agg, int E)
{
    constexpr int NSTRIDE = D / 8;
    long long wid = (long long)((blockIdx.x * (unsigned)blockDim.x + threadIdx.x) >> 5);
    if (wid * 2 >= E) return;
    int lane = threadIdx.x & 31;
    int sl = lane & 15;
    long long e = wid * 2 + (lane >> 4);
    bool valid = (e < E);
    long long ec = valid ? e : (long long)E - 1;

    int s, d;
    if (g_is64) {
        const long long* p = (const long long*)eidx;
        s = (int)p[ec];
        d = (int)p[ec + E];
    } else {
        const int* p = (const int*)eidx;
        s = p[ec];
        d = p[ec + E];
    }
    float nn = norms[s] * norms[d];

    const uint4* ps = fb + (size_t)s * NSTRIDE;
    const uint4* pd = fb + (size_t)d * NSTRIDE;

    float t;
    {
        uint4 a0 = ps[sl];
        uint4 b0 = pd[sl];
        __nv_bfloat162 z2 = __float2bfloat162_rn(0.f);
        __nv_bfloat162 acc0 = z2;
        {
            const __nv_bfloat162* pa = (const __nv_bfloat162*)&a0;
            const __nv_bfloat162* pb = (const __nv_bfloat162*)&b0;
#pragma unroll
            for (int i = 0; i < 4; i++) acc0 = __hfma2(pa[i], pb[i], acc0);
        }
        float2 f0 = __bfloat1622float2(acc0);
        t = f0.x + f0.y;
        if (U4 == 2) {
            uint4 a1 = ps[sl + 16];
            uint4 b1 = pd[sl + 16];
            __nv_bfloat162 acc1 = z2;
            const __nv_bfloat162* pa = (const __nv_bfloat162*)&a1;
            const __nv_bfloat162* pb = (const __nv_bfloat162*)&b1;
#pragma unroll
            for (int i = 0; i < 4; i++) acc1 = __hfma2(pa[i], pb[i], acc1);
            float2 f1 = __bfloat1622float2(acc1);
            t += f1.x + f1.y;
        }
    }
#pragma unroll
    for (int o = 1; o < 16; o <<= 1) t += __shfl_xor_sync(0xffffffffu, t, o);

    float thr = 0.5f * fmaxf(nn, EPSF);
    float margin = BF16_MARGIN * nn;
    bool pass;
    if (fabsf(t - thr) > margin) {
        pass = (t > thr);
    } else {
        unsigned hm = 0xffffu << (lane & 16);
        const float4* fs = (const float4*)(feat + (size_t)s * D);
        const float4* fd = (const float4*)(feat + (size_t)d * D);
        float ex = 0.f;
#pragma unroll
        for (int i = 0; i < D / 64; i++) {
            float4 a = fs[sl + 16 * i];
            float4 b = fd[sl + 16 * i];
            ex += a.x * b.x + a.y * b.y + a.z * b.z + a.w * b.w;
        }
#pragma unroll
        for (int o = 1; o < 16; o <<= 1) ex += __shfl_xor_sync(hm, ex, o);
        pass = (ex > thr);
    }

    if (valid && pass) {
        const float4* fs = (const float4*)(feat + (size_t)s * D);
        float* out = agg + (size_t)d * D;
#pragma unroll
        for (int i = 0; i < D / 64; i++) {
            float4 a = fs[sl + 16 * i];
            asm volatile("red.global.add.v4.f32 [%0], {%1,%2,%3,%4};" ::
                         "l"(out + (sl + 16 * i) * 4),
                         "f"(a.x), "f"(a.y), "f"(a.z), "f"(a.w)
                         : "memory");
        }
    }
}

// ---------------------------------------------------------------------------
// GEMM1 (HMMA): h = relu(agg1 @ W1^T + b1), block tile 128x256, K=128.
// 3-term hi/lo split (exact). Fused epilogue: h, hb, hnorm, agg2 init.
// smem layout (bytes): A_hi[128x136 bf16]=34816, A_lo=34816,
//                      B_hi[256x136 bf16]=69632, B_lo=69632. Stage reuses B.
// ---------------------------------------------------------------------------
#define G1_SA_HI 0
#define G1_SA_LO 34816
#define G1_SB_HI 69632
#define G1_SB_LO 139264
#define G1_SMEM  208896
#define G1_STAGE 69632      /* float stage[128][258] = 132096 B, fits B region */

__global__ __launch_bounds__(512, 1)
void k_gemm1_mma(const float* __restrict__ A,
                 const unsigned* __restrict__ whi, const unsigned* __restrict__ wlo,
                 const float* __restrict__ bias,
                 float* __restrict__ hq, uint4* __restrict__ hbq,
                 float* __restrict__ hnq, float* __restrict__ aggq, int M)
{
    extern __shared__ char smem[];
    int tid = threadIdx.x, wid = tid >> 5, lane = tid & 31;
    int m0 = blockIdx.x * 128;

    // A tile: fp32 -> hi/lo bf16, padded row-major (stride 136 bf16 = 272 B)
    for (int g = tid; g < 2048; g += 512) {
        int r = g >> 4, c = (g & 15) * 8;
        int gr = m0 + r;
        if (gr >= M) gr = M - 1;
        const float4* p = (const float4*)(A + (size_t)gr * 128 + c);
        float4 u = p[0], w = p[1];
        unsigned hi[4], lo[4];
        split2bf(u.x, u.y, hi[0], lo[0]);
        split2bf(u.z, u.w, hi[1], lo[1]);
        split2bf(w.x, w.y, hi[2], lo[2]);
        split2bf(w.z, w.w, hi[3], lo[3]);
        size_t off = (size_t)r * 272 + c * 2;
        *(uint2*)(smem + G1_SA_HI + off)     = make_uint2(hi[0], hi[1]);
        *(uint2*)(smem + G1_SA_HI + off + 8) = make_uint2(hi[2], hi[3]);
        *(uint2*)(smem + G1_SA_LO + off)     = make_uint2(lo[0], lo[1]);
        *(uint2*)(smem + G1_SA_LO + off + 8) = make_uint2(lo[2], lo[3]);
    }
    // B tiles (preconverted, linear [n][k]) -> padded smem
    {
        const uint4* bh = (const uint4*)whi;
        const uint4* bl = (const uint4*)wlo;
        for (int g = tid; g < 4096; g += 512) {
            int n = g >> 4, q = g & 15;
            size_t off = (size_t)n * 272 + q * 16;
            *(uint4*)(smem + G1_SB_HI + off) = bh[g];
            *(uint4*)(smem + G1_SB_LO + off) = bl[g];
        }
    }
    __syncthreads();

    uint32_t sbase = smem_u32(smem);
    int wm = wid >> 2, wn = wid & 3;          // 4x4 warp grid, tile 32x64
    int arow = wm * 32 + (lane & 15);
    int acol = (lane >> 4) * 8;
    int brow = wn * 64 + (lane & 7);
    int bcol = ((lane >> 3) & 1) * 8;

    float acc[2][8][4];
#pragma unroll
    for (int i = 0; i < 2; i++)
#pragma unroll
        for (int j = 0; j < 8; j++)
#pragma unroll
            for (int k = 0; k < 4; k++) acc[i][j][k] = 0.f;

#pragma unroll
    for (int pass = 0; pass < 3; pass++) {
        uint32_t sa = sbase + (pass == 2 ? G1_SA_LO : G1_SA_HI);
        uint32_t sb = sbase + (pass == 1 ? G1_SB_LO : G1_SB_HI);
        uint32_t aaddr = sa + (uint32_t)(arow * 272 + acol * 2);
        uint32_t baddr = sb + (uint32_t)(brow * 272 + bcol * 2);
#pragma unroll
        for (int kc = 0; kc < 8; kc++) {
            uint32_t af0[4], af1[4];
            ldsm_x4(af0, aaddr + kc * 32);
            ldsm_x4(af1, aaddr + 16 * 272 + kc * 32);
#pragma unroll
            for (int nf = 0; nf < 8; nf++) {
                uint32_t bf[2];
                ldsm_x2(bf, baddr + nf * 8 * 272 + kc * 32);
                mma_bf16(acc[0][nf], af0, bf);
                mma_bf16(acc[1][nf], af1, bf);
            }
        }
    }
    __syncthreads();

    // Stage accumulators to smem (stride 258 f32)
    float* stage = (float*)(smem + G1_STAGE);
    {
        int srow = wm * 32 + (lane >> 2);
        int scol = wn * 64 + 2 * (lane & 3);
#pragma unroll
        for (int mf = 0; mf < 2; mf++)
#pragma unroll
            for (int nf = 0; nf < 8; nf++) {
                float* p = stage + (size_t)(srow + mf * 16) * 258 + scol + nf * 8;
                *(float2*)p = make_float2(acc[mf][nf][0], acc[mf][nf][1]);
                *(float2*)(p + 8 * 258) = make_float2(acc[mf][nf][2], acc[mf][nf][3]);
            }
    }
    __syncthreads();

    // Epilogue: row-per-lane; warp = (sub rows) x (cch col-chunk of 64)
    {
        int sub = wid & 3, cch = wid >> 2;
        int r_local = sub * 32 + lane;
        int gm = m0 + r_local;
        const float* srw = stage + (size_t)r_local * 258 + cch * 64;
        float vv[64];
        float n2 = 0.f;
#pragma unroll
        for (int i = 0; i < 32; i++) {
            float2 t = *(const float2*)(srw + 2 * i);
            float v0 = fmaxf(t.x + __ldg(&bias[cch * 64 + 2 * i]), 0.f);
            float v1 = fmaxf(t.y + __ldg(&bias[cch * 64 + 2 * i + 1]), 0.f);
            vv[2 * i] = v0;
            vv[2 * i + 1] = v1;
            n2 += v0 * v0 + v1 * v1;
        }
        float* n2p = (float*)smem;  // A region, free now
        n2p[cch * 128 + r_local] = n2;
        __syncthreads();
        float tot = n2p[r_local] + n2p[128 + r_local] + n2p[256 + r_local] + n2p[384 + r_local];
        bool pass = tot > 0.5f * fmaxf(tot, EPSF);

        if (gm < M) {
            if (cch == 0) hnq[gm] = sqrtf(tot);
            float4* hp4 = (float4*)(hq + (size_t)gm * 256 + cch * 64);
            float4* ap4 = (float4*)(aggq + (size_t)gm * 256 + cch * 64);
            uint4* hbp = hbq + (size_t)gm * 32 + cch * 8;
            float4 z4 = make_float4(0.f, 0.f, 0.f, 0.f);
#pragma unroll
            for (int i = 0; i < 16; i++) {
                float4 t = make_float4(vv[4 * i], vv[4 * i + 1], vv[4 * i + 2], vv[4 * i + 3]);
                hp4[i] = t;
                ap4[i] = pass ? t : z4;
            }
#pragma unroll
            for (int i = 0; i < 8; i++) {
                hbp[i] = make_uint4(pack2bf(vv[8 * i], vv[8 * i + 1]),
                                    pack2bf(vv[8 * i + 2], vv[8 * i + 3]),
                                    pack2bf(vv[8 * i + 4], vv[8 * i + 5]),
                                    pack2bf(vv[8 * i + 6], vv[8 * i + 7]));
            }
        }
    }
}

// ---------------------------------------------------------------------------
// GEMM2 (HMMA): out = log_softmax(agg2 @ W2^T + b2), tile 128x64, K=256.
// smem: A_hi/lo[128x264 bf16]=67584 ea, B_hi/lo[64x264 bf16]=33792 ea.
// ---------------------------------------------------------------------------
#define G2_SA_HI 0
#define G2_SA_LO 67584
#define G2_SB_HI 135168
#define G2_SB_LO 168960
#define G2_SMEM  202752
#define G2_STAGE 135168     /* float stage[128][66] = 33792 B */

__global__ __launch_bounds__(512, 1)
void k_gemm2_mma(const float* __restrict__ A,
                 const unsigned* __restrict__ whi, const unsigned* __restrict__ wlo,
                 const float* __restrict__ bias,
                 float* __restrict__ outq, int M)
{
    extern __shared__ char smem[];
    int tid = threadIdx.x, wid = tid >> 5, lane = tid & 31;
    int m0 = blockIdx.x * 128;

    // A tile: 128 x 256 fp32 -> hi/lo (stride 264 bf16 = 528 B)
    for (int g = tid; g < 4096; g += 512) {
        int r = g >> 5, c = (g & 31) * 8;
        int gr = m0 + r;
        if (gr >= M) gr = M - 1;
        const float4* p = (const float4*)(A + (size_t)gr * 256 + c);
        float4 u = p[0], w = p[1];
        unsigned hi[4], lo[4];
        split2bf(u.x, u.y, hi[0], lo[0]);
        split2bf(u.z, u.w, hi[1], lo[1]);
        split2bf(w.x, w.y, hi[2], lo[2]);
        split2bf(w.z, w.w, hi[3], lo[3]);
        size_t off = (size_t)r * 528 + c * 2;
        *(uint2*)(smem + G2_SA_HI + off)     = make_uint2(hi[0], hi[1]);
        *(uint2*)(smem + G2_SA_HI + off + 8) = make_uint2(hi[2], hi[3]);
        *(uint2*)(smem + G2_SA_LO + off)     = make_uint2(lo[0], lo[1]);
        *(uint2*)(smem + G2_SA_LO + off + 8) = make_uint2(lo[2], lo[3]);
    }
    // B tiles: 64 x 256 bf16
    {
        const uint4* bh = (const uint4*)whi;
        const uint4* bl = (const uint4*)wlo;
        for (int g = tid; g < 2048; g += 512) {
            int n = g >> 5, q = g & 31;
            size_t off = (size_t)n * 528 + q * 16;
            *(uint4*)(smem + G2_SB_HI + off) = bh[g];
            *(uint4*)(smem + G2_SB_LO + off) = bl[g];
        }
    }
    __syncthreads();

    uint32_t sbase = smem_u32(smem);
    int wm = wid >> 2, wn = wid & 3;        // warp tile 32x16
    int arow = wm * 32 + (lane & 15);
    int acol = (lane >> 4) * 8;
    int brow = wn * 16 + (lane & 7);
    int bcol = ((lane >> 3) & 1) * 8;

    float acc[2][2][4];
#pragma unroll
    for (int i = 0; i < 2; i++)
#pragma unroll
        for (int j = 0; j < 2; j++)
#pragma unroll
            for (int k = 0; k < 4; k++) acc[i][j][k] = 0.f;

#pragma unroll
    for (int pass = 0; pass < 3; pass++) {
        uint32_t sa = sbase + (pass == 2 ? G2_SA_LO : G2_SA_HI);
        uint32_t sb = sbase + (pass == 1 ? G2_SB_LO : G2_SB_HI);
        uint32_t aaddr = sa + (uint32_t)(arow * 528 + acol * 2);
        uint32_t baddr = sb + (uint32_t)(brow * 528 + bcol * 2);
#pragma unroll
        for (int kc = 0; kc < 16; kc++) {
            uint32_t af0[4], af1[4];
            ldsm_x4(af0, aaddr + kc * 32);
            ldsm_x4(af1, aaddr + 16 * 528 + kc * 32);
#pragma unroll
            for (int nf = 0; nf < 2; nf++) {
                uint32_t bf[2];
                ldsm_x2(bf, baddr + nf * 8 * 528 + kc * 32);
                mma_bf16(acc[0][nf], af0, bf);
                mma_bf16(acc[1][nf], af1, bf);
            }
        }
    }
    __syncthreads();

    float* stage = (float*)(smem + G2_STAGE);
    {
        int srow = wm * 32 + (lane >> 2);
        int scol = wn * 16 + 2 * (lane & 3);
#pragma unroll
        for (int mf = 0; mf < 2; mf++)
#pragma unroll
            for (int nf = 0; nf < 2; nf++) {
                float* p = stage + (size_t)(srow + mf * 16) * 66 + scol + nf * 8;
                *(float2*)p = make_float2(acc[mf][nf][0], acc[mf][nf][1]);
                *(float2*)(p + 8 * 66) = make_float2(acc[mf][nf][2], acc[mf][nf][3]);
            }
    }
    __syncthreads();

    if (wid < 4) {
        int r_local = wid * 32 + lane;
        int gm = m0 + r_local;
        const float* srw = stage + (size_t)r_local * 66;
        float v[64];
#pragma unroll
        for (int i = 0; i < 32; i++) {
            float2 t = *(const float2*)(srw + 2 * i);
            v[2 * i] = t.x + __ldg(&bias[2 * i]);
            v[2 * i + 1] = t.y + __ldg(&bias[2 * i + 1]);
        }
        float mx = v[0];
#pragma unroll
        for (int i = 1; i < 64; i++) mx = fmaxf(mx, v[i]);
        float sm = 0.f;
#pragma unroll
        for (int i = 0; i < 64; i++) sm += __expf(v[i] - mx);
        float l = mx + __logf(sm);
        if (gm < M) {
            float4* op = (float4*)(outq + (size_t)gm * 64);
#pragma unroll
            for (int i = 0; i < 16; i++)
                op[i] = make_float4(v[4 * i] - l, v[4 * i + 1] - l,
                                    v[4 * i + 2] - l, v[4 * i + 3] - l);
        }
    }
}

// ---------------------------------------------------------------------------
extern "C" void kernel_launch(void* const* d_in, const int* in_sizes, int n_in,
                              void* d_out, int out_size)
{
    const float* x   = (const float*)d_in[0];
    const void*  eix = d_in[1];
    const float* W1  = (const float*)d_in[2];
    const float* b1  = (const float*)d_in[3];
    const float* W2  = (const float*)d_in[4];
    const float* b2  = (const float*)d_in[5];
    float* out = (float*)d_out;

    int N = in_sizes[0] / D1;      // 50000
    int E = in_sizes[1] / 2;       // 800000
    (void)n_in; (void)out_size;

    float *agg1, *h, *agg2, *xn, *hn;
    uint4 *xb, *hb;
    unsigned *w1hi, *w1lo, *w2hi, *w2lo;
    cudaGetSymbolAddress((void**)&agg1, g_agg1_);
    cudaGetSymbolAddress((void**)&h,    g_h_);
    cudaGetSymbolAddress((void**)&agg2, g_agg2_);
    cudaGetSymbolAddress((void**)&xb,   g_xb_);
    cudaGetSymbolAddress((void**)&hb,   g_hb_);
    cudaGetSymbolAddress((void**)&xn,   g_xnorm);
    cudaGetSymbolAddress((void**)&hn,   g_hnorm);
    cudaGetSymbolAddress((void**)&w1hi, g_w1hi);
    cudaGetSymbolAddress((void**)&w1lo, g_w1lo);
    cudaGetSymbolAddress((void**)&w2hi, g_w2hi);
    cudaGetSymbolAddress((void**)&w2lo, g_w2lo);

    static int smem_set = 0;
    if (!smem_set) {
        cudaFuncSetAttribute(k_gemm1_mma, cudaFuncAttributeMaxDynamicSharedMemorySize, G1_SMEM);
        cudaFuncSetAttribute(k_gemm2_mma, cudaFuncAttributeMaxDynamicSharedMemorySize, G2_SMEM);
        smem_set = 1;
    }

    k_init_flag<<<1, 1>>>();
    k_detect64<<<(E + 255) / 256, 256>>>(eix, E, N);
    k_wsplit<<<(16384 + 255) / 256, 256>>>(W1, w1hi, w1lo, 16384);
    k_wsplit<<<(8192 + 255) / 256, 256>>>(W2, w2hi, w2lo, 8192);

    int nodeBlocks = (N * 32 + 255) / 256;
    long long warps = ((long long)E + 1) / 2;
    int edgeBlocks = (int)((warps * 32 + 255) / 256);
    int mBlocks = (N + 127) / 128;

    // ---- Layer 1 ----
    k_norms_init<D1><<<nodeBlocks, 256>>>(x, xn, agg1, (uint2*)xb, N);
    k_edge_half<D1, 1><<<edgeBlocks, 256>>>(x, xb, xn, eix, agg1, E);
    k_gemm1_mma<<<mBlocks, 512, G1_SMEM>>>(agg1, w1hi, w1lo, b1, h, hb, hn, agg2, N);

    // ---- Layer 2 ----
    k_edge_half<D2, 2><<<edgeBlocks, 256>>>(h, hb, hn, eix, agg2, E);
    k_gemm2_mma<<<mBlocks, 512, G2_SMEM>>>(agg2, w2hi, w2lo, b2, out, N);
}

// round 9
// speedup vs baseline: 1.1698x; 1.1698x over previous
#include <cuda_runtime.h>
#include <cuda_bf16.h>
#include <stdint.h>
#include <math.h>

#define EPSF 1e-8f
#define NMAX 50000
#define D1 128
#define D2 256
#define BF16_MARGIN 0.02f

typedef unsigned long long u64;

// ---------------------------------------------------------------------------
// Scratch (device globals — no allocation allowed).
// ---------------------------------------------------------------------------
__device__ float4 g_agg1_[(size_t)NMAX * D1 / 4];
__device__ float4 g_h_[(size_t)NMAX * D2 / 4];
__device__ float4 g_agg2_[(size_t)NMAX * D2 / 4];
__device__ uint4  g_xb_[(size_t)NMAX * D1 / 8];
__device__ uint4  g_hb_[(size_t)NMAX * D2 / 8];
__device__ float  g_xnorm[NMAX];
__device__ float  g_hnorm[NMAX];
__device__ int    g_is64;

// ---------------------------------------------------------------------------
// helpers
// ---------------------------------------------------------------------------
__device__ __forceinline__ unsigned pack2bf(float a, float b) {
    __nv_bfloat162 t = __floats2bfloat162_rn(a, b);
    return *(unsigned*)&t;
}
__device__ __forceinline__ uint2 pack_bf16x4(float4 v) {
    uint2 r;
    r.x = pack2bf(v.x, v.y);
    r.y = pack2bf(v.z, v.w);
    return r;
}
// packed f32x2 FMA (B300 FFMA2)
__device__ __forceinline__ u64 dup2(float a) {
    u64 r;
    asm("mov.b64 %0, {%1, %1};" : "=l"(r) : "f"(a));
    return r;
}
__device__ __forceinline__ u64 fma2(u64 a, u64 b, u64 c) {
    u64 d;
    asm("fma.rn.f32x2 %0, %1, %2, %3;" : "=l"(d) : "l"(a), "l"(b), "l"(c));
    return d;
}
__device__ __forceinline__ float2 unpk(u64 a) {
    float2 f;
    asm("mov.b64 {%0, %1}, %2;" : "=f"(f.x), "=f"(f.y) : "l"(a));
    return f;
}

// ---------------------------------------------------------------------------
// small setup kernels
// ---------------------------------------------------------------------------
__global__ void k_init_flag() { g_is64 = 1; }

__global__ void k_detect64(const void* __restrict__ eidx, int E, int N) {
    int i = blockIdx.x * blockDim.x + threadIdx.x;
    if (i < E) {
        long long v = ((const long long*)eidx)[i];
        if (v < 0 || v >= (long long)N) g_is64 = 0;
    }
}

// ---------------------------------------------------------------------------
// Per-node norms + self-loop init + bf16 conversion (layer-1 input x).
// ---------------------------------------------------------------------------
template<int D>
__global__ void k_norms_init(const float* __restrict__ feat,
                             float* __restrict__ norms,
                             float* __restrict__ agg,
                             uint2* __restrict__ fb, int N)
{
    int node = (blockIdx.x * blockDim.x + threadIdx.x) >> 5;
    int lane = threadIdx.x & 31;
    if (node >= N) return;
    const float4* f = (const float4*)(feat + (size_t)node * D);
    float4* a = (float4*)(agg + (size_t)node * D);
    uint2* fbr = fb + (size_t)node * (D / 4);
    float4 v[D / 128];
    float n2 = 0.f;
#pragma unroll
    for (int i = 0; i < D / 128; i++) {
        v[i] = f[lane + 32 * i];
        n2 += v[i].x * v[i].x + v[i].y * v[i].y + v[i].z * v[i].z + v[i].w * v[i].w;
    }
#pragma unroll
    for (int i = 0; i < D / 128; i++) fbr[lane + 32 * i] = pack_bf16x4(v[i]);
#pragma unroll
    for (int o = 16; o; o >>= 1) n2 += __shfl_xor_sync(0xffffffffu, n2, o);
    float nrm = sqrtf(n2);
    if (lane == 0) norms[node] = nrm;
    float denom = fmaxf(nrm * nrm, EPSF);
    bool pass = n2 > 0.5f * denom;
    float4 z = make_float4(0.f, 0.f, 0.f, 0.f);
#pragma unroll
    for (int i = 0; i < D / 128; i++) a[lane + 32 * i] = pass ? v[i] : z;
}

// ---------------------------------------------------------------------------
// Edge pass, half-warp per edge (R5, proven).
// ---------------------------------------------------------------------------
template<int D, int U4>
__global__ void k_edge_half(const float* __restrict__ feat,
                            const uint4* __restrict__ fb,
                            const float* __restrict__ norms,
                            const void* __restrict__ eidx,
                            float* __restrict__ agg, int E)
{
    constexpr int NSTRIDE = D / 8;
    long long wid = (long long)((blockIdx.x * (unsigned)blockDim.x + threadIdx.x) >> 5);
    if (wid * 2 >= E) return;
    int lane = threadIdx.x & 31;
    int sl = lane & 15;
    long long e = wid * 2 + (lane >> 4);
    bool valid = (e < E);
    long long ec = valid ? e : (long long)E - 1;

    int s, d;
    if (g_is64) {
        const long long* p = (const long long*)eidx;
        s = (int)p[ec];
        d = (int)p[ec + E];
    } else {
        const int* p = (const int*)eidx;
        s = p[ec];
        d = p[ec + E];
    }
    float nn = norms[s] * norms[d];

    const uint4* ps = fb + (size_t)s * NSTRIDE;
    const uint4* pd = fb + (size_t)d * NSTRIDE;

    float t;
    {
        uint4 a0 = ps[sl];
        uint4 b0 = pd[sl];
        __nv_bfloat162 z2 = __float2bfloat162_rn(0.f);
        __nv_bfloat162 acc0 = z2;
        {
            const __nv_bfloat162* pa = (const __nv_bfloat162*)&a0;
            const __nv_bfloat162* pb = (const __nv_bfloat162*)&b0;
#pragma unroll
            for (int i = 0; i < 4; i++) acc0 = __hfma2(pa[i], pb[i], acc0);
        }
        float2 f0 = __bfloat1622float2(acc0);
        t = f0.x + f0.y;
        if (U4 == 2) {
            uint4 a1 = ps[sl + 16];
            uint4 b1 = pd[sl + 16];
            __nv_bfloat162 acc1 = z2;
            const __nv_bfloat162* pa = (const __nv_bfloat162*)&a1;
            const __nv_bfloat162* pb = (const __nv_bfloat162*)&b1;
#pragma unroll
            for (int i = 0; i < 4; i++) acc1 = __hfma2(pa[i], pb[i], acc1);
            float2 f1 = __bfloat1622float2(acc1);
            t += f1.x + f1.y;
        }
    }
#pragma unroll
    for (int o = 1; o < 16; o <<= 1) t += __shfl_xor_sync(0xffffffffu, t, o);

    float thr = 0.5f * fmaxf(nn, EPSF);
    float margin = BF16_MARGIN * nn;
    bool pass;
    if (fabsf(t - thr) > margin) {
        pass = (t > thr);
    } else {
        unsigned hm = 0xffffu << (lane & 16);
        const float4* fs = (const float4*)(feat + (size_t)s * D);
        const float4* fd = (const float4*)(feat + (size_t)d * D);
        float ex = 0.f;
#pragma unroll
        for (int i = 0; i < D / 64; i++) {
            float4 a = fs[sl + 16 * i];
            float4 b = fd[sl + 16 * i];
            ex += a.x * b.x + a.y * b.y + a.z * b.z + a.w * b.w;
        }
#pragma unroll
        for (int o = 1; o < 16; o <<= 1) ex += __shfl_xor_sync(hm, ex, o);
        pass = (ex > thr);
    }

    if (valid && pass) {
        const float4* fs = (const float4*)(feat + (size_t)s * D);
        float* out = agg + (size_t)d * D;
#pragma unroll
        for (int i = 0; i < D / 64; i++) {
            float4 a = fs[sl + 16 * i];
            asm volatile("red.global.add.v4.f32 [%0], {%1,%2,%3,%4};" ::
                         "l"(out + (sl + 16 * i) * 4),
                         "f"(a.x), "f"(a.y), "f"(a.z), "f"(a.w)
                         : "memory");
        }
    }
}

// ---------------------------------------------------------------------------
// GEMM1 (f32x2): h = relu(agg1 @ W1^T + b1). Block 64x256, K=128, 256 thr.
// Each warp (ty) owns 8 full rows -> fused epilogue: h, hb, hnorm, agg2 init.
// ---------------------------------------------------------------------------
__global__ __launch_bounds__(256)
void k_gemm1_f2(const float* __restrict__ A, const float* __restrict__ W,
                const float* __restrict__ bias,
                float* __restrict__ hq, uint4* __restrict__ hbq,
                float* __restrict__ hnq, float* __restrict__ aggq, int M)
{
    __shared__ float As[16][64];
    __shared__ float Ws[16][256];
    int tid = threadIdx.x;
    int tx = tid & 31;          // 32 col-chunks of 8
    int ty = tid >> 5;          // 8 row-groups of 8 (= warp id)
    int m0 = blockIdx.x * 64;

    u64 acc[8][4];
#pragma unroll
    for (int i = 0; i < 8; i++)
#pragma unroll
        for (int j = 0; j < 4; j++) acc[i][j] = 0ull;

    for (int k0 = 0; k0 < 128; k0 += 16) {
        // A tile: 64 rows x 16 cols (256 float4 loads, 1/thread)
        {
            int m = tid >> 2, kq = tid & 3;
            int gm = m0 + m;
            if (gm >= M) gm = M - 1;
            float4 v = *(const float4*)(A + (size_t)gm * 128 + k0 + kq * 4);
            As[kq * 4 + 0][m] = v.x;
            As[kq * 4 + 1][m] = v.y;
            As[kq * 4 + 2][m] = v.z;
            As[kq * 4 + 3][m] = v.w;
        }
        // W tile: 256 rows x 16 cols (1024 float4 loads, 4/thread)
#pragma unroll
        for (int i = tid; i < 1024; i += 256) {
            int n = i >> 2, kq = i & 3;
            float4 v = *(const float4*)(W + (size_t)n * 128 + k0 + kq * 4);
            Ws[kq * 4 + 0][n] = v.x;
            Ws[kq * 4 + 1][n] = v.y;
            Ws[kq * 4 + 2][n] = v.z;
            Ws[kq * 4 + 3][n] = v.w;
        }
        __syncthreads();
#pragma unroll
        for (int k = 0; k < 16; k++) {
            u64 rm2[8], rn[4];
#pragma unroll
            for (int i = 0; i < 8; i++) rm2[i] = dup2(As[k][ty * 8 + i]);
#pragma unroll
            for (int j = 0; j < 4; j++) rn[j] = *(const u64*)&Ws[k][tx * 8 + 2 * j];
#pragma unroll
            for (int i = 0; i < 8; i++)
#pragma unroll
                for (int j = 0; j < 4; j++)
                    acc[i][j] = fma2(rm2[i], rn[j], acc[i][j]);
        }
        __syncthreads();
    }

    // bias for this lane's 8 cols
    float4 b0 = *(const float4*)&bias[tx * 8];
    float4 b1 = *(const float4*)&bias[tx * 8 + 4];
    float bb[8] = {b0.x, b0.y, b0.z, b0.w, b1.x, b1.y, b1.z, b1.w};

#pragma unroll
    for (int i = 0; i < 8; i++) {
        int gm = m0 + ty * 8 + i;
        float v[8];
#pragma unroll
        for (int j = 0; j < 4; j++) {
            float2 t = unpk(acc[i][j]);
            v[2 * j] = t.x;
            v[2 * j + 1] = t.y;
        }
        float n2 = 0.f;
#pragma unroll
        for (int c = 0; c < 8; c++) {
            v[c] = fmaxf(v[c] + bb[c], 0.f);
            n2 += v[c] * v[c];
        }
#pragma unroll
        for (int o = 16; o; o >>= 1) n2 += __shfl_xor_sync(0xffffffffu, n2, o);
        bool pass = n2 > 0.5f * fmaxf(n2, EPSF);
        if (gm < M) {
            if (tx == 0) hnq[gm] = sqrtf(n2);
            float4 t0 = make_float4(v[0], v[1], v[2], v[3]);
            float4 t1 = make_float4(v[4], v[5], v[6], v[7]);
            float4* hp = (float4*)(hq + (size_t)gm * 256 + tx * 8);
            hp[0] = t0;
            hp[1] = t1;
            float4 z4 = make_float4(0.f, 0.f, 0.f, 0.f);
            float4* ap = (float4*)(aggq + (size_t)gm * 256 + tx * 8);
            ap[0] = pass ? t0 : z4;
            ap[1] = pass ? t1 : z4;
            hbq[(size_t)gm * 32 + tx] =
                make_uint4(pack2bf(v[0], v[1]), pack2bf(v[2], v[3]),
                           pack2bf(v[4], v[5]), pack2bf(v[6], v[7]));
        }
    }
}

// ---------------------------------------------------------------------------
// GEMM2 (f32x2): out = log_softmax(agg2 @ W2^T + b2). Block 128x64, K=256.
// 256 thr: tx 0..15 (4 cols each), ty 0..15 (8 rows each). LSM over 16 lanes.
// ---------------------------------------------------------------------------
__global__ __launch_bounds__(256)
void k_gemm2_f2(const float* __restrict__ A, const float* __restrict__ W,
                const float* __restrict__ bias,
                float* __restrict__ outq, int M)
{
    __shared__ float As[16][128];
    __shared__ float Ws[16][64];
    int tid = threadIdx.x;
    int tx = tid & 15;
    int ty = tid >> 4;
    int m0 = blockIdx.x * 128;

    u64 acc[8][2];
#pragma unroll
    for (int i = 0; i < 8; i++) {
        acc[i][0] = 0ull;
        acc[i][1] = 0ull;
    }

    for (int k0 = 0; k0 < 256; k0 += 16) {
        // A tile: 128 x 16 (512 float4 loads, 2/thread)
#pragma unroll
        for (int i = tid; i < 512; i += 256) {
            int m = i >> 2, kq = i & 3;
            int gm = m0 + m;
            if (gm >= M) gm = M - 1;
            float4 v = *(const float4*)(A + (size_t)gm * 256 + k0 + kq * 4);
            As[kq * 4 + 0][m] = v.x;
            As[kq * 4 + 1][m] = v.y;
            As[kq * 4 + 2][m] = v.z;
            As[kq * 4 + 3][m] = v.w;
        }
        // W tile: 64 x 16 (256 float4 loads, 1/thread)
        {
            int n = tid >> 2, kq = tid & 3;
            float4 v = *(const float4*)(W + (size_t)n * 256 + k0 + kq * 4);
            Ws[kq * 4 + 0][n] = v.x;
            Ws[kq * 4 + 1][n] = v.y;
            Ws[kq * 4 + 2][n] = v.z;
            Ws[kq * 4 + 3][n] = v.w;
        }
        __syncthreads();
#pragma unroll
        for (int k = 0; k < 16; k++) {
            u64 rm2[8], rn[2];
#pragma unroll
            for (int i = 0; i < 8; i++) rm2[i] = dup2(As[k][ty * 8 + i]);
            rn[0] = *(const u64*)&Ws[k][tx * 4];
            rn[1] = *(const u64*)&Ws[k][tx * 4 + 2];
#pragma unroll
            for (int i = 0; i < 8; i++) {
                acc[i][0] = fma2(rm2[i], rn[0], acc[i][0]);
                acc[i][1] = fma2(rm2[i], rn[1], acc[i][1]);
            }
        }
        __syncthreads();
    }

    float4 bv = *(const float4*)&bias[tx * 4];
    float bb[4] = {bv.x, bv.y, bv.z, bv.w};

#pragma unroll
    for (int i = 0; i < 8; i++) {
        int gm = m0 + ty * 8 + i;
        float v[4];
        float2 t0 = unpk(acc[i][0]);
        float2 t1 = unpk(acc[i][1]);
        v[0] = t0.x + bb[0];
        v[1] = t0.y + bb[1];
        v[2] = t1.x + bb[2];
        v[3] = t1.y + bb[3];
        // log_softmax over the 16 lanes (tx) holding this row's 64 cols
        float mx = fmaxf(fmaxf(v[0], v[1]), fmaxf(v[2], v[3]));
#pragma unroll
        for (int o = 1; o < 16; o <<= 1)
            mx = fmaxf(mx, __shfl_xor_sync(0xffffffffu, mx, o));
        float sm = __expf(v[0] - mx) + __expf(v[1] - mx) +
                   __expf(v[2] - mx) + __expf(v[3] - mx);
#pragma unroll
        for (int o = 1; o < 16; o <<= 1)
            sm += __shfl_xor_sync(0xffffffffu, sm, o);
        float l = mx + __logf(sm);
        if (gm < M) {
            *(float4*)(outq + (size_t)gm * 64 + tx * 4) =
                make_float4(v[0] - l, v[1] - l, v[2] - l, v[3] - l);
        }
    }
}

// ---------------------------------------------------------------------------
extern "C" void kernel_launch(void* const* d_in, const int* in_sizes, int n_in,
                              void* d_out, int out_size)
{
    const float* x   = (const float*)d_in[0];
    const void*  eix = d_in[1];
    const float* W1  = (const float*)d_in[2];
    const float* b1  = (const float*)d_in[3];
    const float* W2  = (const float*)d_in[4];
    const float* b2  = (const float*)d_in[5];
    float* out = (float*)d_out;

    int N = in_sizes[0] / D1;      // 50000
    int E = in_sizes[1] / 2;       // 800000
    (void)n_in; (void)out_size;

    float *agg1, *h, *agg2, *xn, *hn;
    uint4 *xb, *hb;
    cudaGetSymbolAddress((void**)&agg1, g_agg1_);
    cudaGetSymbolAddress((void**)&h,    g_h_);
    cudaGetSymbolAddress((void**)&agg2, g_agg2_);
    cudaGetSymbolAddress((void**)&xb,   g_xb_);
    cudaGetSymbolAddress((void**)&hb,   g_hb_);
    cudaGetSymbolAddress((void**)&xn,   g_xnorm);
    cudaGetSymbolAddress((void**)&hn,   g_hnorm);

    k_init_flag<<<1, 1>>>();
    k_detect64<<<(E + 255) / 256, 256>>>(eix, E, N);

    int nodeBlocks = (N * 32 + 255) / 256;
    long long warps = ((long long)E + 1) / 2;
    int edgeBlocks = (int)((warps * 32 + 255) / 256);

    // ---- Layer 1 ----
    k_norms_init<D1><<<nodeBlocks, 256>>>(x, xn, agg1, (uint2*)xb, N);
    k_edge_half<D1, 1><<<edgeBlocks, 256>>>(x, xb, xn, eix, agg1, E);
    k_gemm1_f2<<<(N + 63) / 64, 256>>>(agg1, W1, b1, h, hb, hn, agg2, N);

    // ---- Layer 2 ----
    k_edge_half<D2, 2><<<edgeBlocks, 256>>>(h, hb, hn, eix, agg2, E);
    k_gemm2_f2<<<(N + 127) / 128, 256>>>(agg2, W2, b2, out, N);
}

// round 10
// speedup vs baseline: 1.2744x; 1.0894x over previous
#include <cuda_runtime.h>
#include <cuda_bf16.h>
#include <stdint.h>
#include <math.h>

#define EPSF 1e-8f
#define NMAX 50000
#define D1 128
#define D2 256
#define BF16_MARGIN 0.02f

typedef unsigned long long u64;

// ---------------------------------------------------------------------------
// Scratch (device globals — no allocation allowed).
// ---------------------------------------------------------------------------
__device__ float4 g_agg1_[(size_t)NMAX * D1 / 4];
__device__ float4 g_h_[(size_t)NMAX * D2 / 4];
__device__ float4 g_agg2_[(size_t)NMAX * D2 / 4];
__device__ uint4  g_xb_[(size_t)NMAX * D1 / 8];
__device__ uint4  g_hb_[(size_t)NMAX * D2 / 8];
__device__ float  g_xnorm[NMAX];
__device__ float  g_hnorm[NMAX];
__device__ int    g_is64;

// ---------------------------------------------------------------------------
// helpers
// ---------------------------------------------------------------------------
__device__ __forceinline__ unsigned pack2bf(float a, float b) {
    __nv_bfloat162 t = __floats2bfloat162_rn(a, b);
    return *(unsigned*)&t;
}
__device__ __forceinline__ uint2 pack_bf16x4(float4 v) {
    uint2 r;
    r.x = pack2bf(v.x, v.y);
    r.y = pack2bf(v.z, v.w);
    return r;
}
// packed f32x2 FMA (B300 FFMA2)
__device__ __forceinline__ u64 dup2(float a) {
    u64 r;
    asm("mov.b64 %0, {%1, %1};" : "=l"(r) : "f"(a));
    return r;
}
__device__ __forceinline__ u64 fma2(u64 a, u64 b, u64 c) {
    u64 d;
    asm("fma.rn.f32x2 %0, %1, %2, %3;" : "=l"(d) : "l"(a), "l"(b), "l"(c));
    return d;
}
__device__ __forceinline__ float2 unpk(u64 a) {
    float2 f;
    asm("mov.b64 {%0, %1}, %2;" : "=f"(f.x), "=f"(f.y) : "l"(a));
    return f;
}

// ---------------------------------------------------------------------------
// small setup kernels
// ---------------------------------------------------------------------------
__global__ void k_init_flag() { g_is64 = 1; }

__global__ void k_detect64(const void* __restrict__ eidx, int E, int N) {
    int i = blockIdx.x * blockDim.x + threadIdx.x;
    if (i < E) {
        long long v = ((const long long*)eidx)[i];
        if (v < 0 || v >= (long long)N) g_is64 = 0;
    }
}

// ---------------------------------------------------------------------------
// Per-node norms + self-loop init + bf16 conversion (layer-1 input x).
// ---------------------------------------------------------------------------
template<int D>
__global__ void k_norms_init(const float* __restrict__ feat,
                             float* __restrict__ norms,
                             float* __restrict__ agg,
                             uint2* __restrict__ fb, int N)
{
    int node = (blockIdx.x * blockDim.x + threadIdx.x) >> 5;
    int lane = threadIdx.x & 31;
    if (node >= N) return;
    const float4* f = (const float4*)(feat + (size_t)node * D);
    float4* a = (float4*)(agg + (size_t)node * D);
    uint2* fbr = fb + (size_t)node * (D / 4);
    float4 v[D / 128];
    float n2 = 0.f;
#pragma unroll
    for (int i = 0; i < D / 128; i++) {
        v[i] = f[lane + 32 * i];
        n2 += v[i].x * v[i].x + v[i].y * v[i].y + v[i].z * v[i].z + v[i].w * v[i].w;
    }
#pragma unroll
    for (int i = 0; i < D / 128; i++) fbr[lane + 32 * i] = pack_bf16x4(v[i]);
#pragma unroll
    for (int o = 16; o; o >>= 1) n2 += __shfl_xor_sync(0xffffffffu, n2, o);
    float nrm = sqrtf(n2);
    if (lane == 0) norms[node] = nrm;
    float denom = fmaxf(nrm * nrm, EPSF);
    bool pass = n2 > 0.5f * denom;
    float4 z = make_float4(0.f, 0.f, 0.f, 0.f);
#pragma unroll
    for (int i = 0; i < D / 128; i++) a[lane + 32 * i] = pass ? v[i] : z;
}

// ---------------------------------------------------------------------------
// Edge pass, quarter-warp per edge (8 lanes/edge, 4 edges/warp).
// U = uint4 bf16 loads per lane per endpoint = D/64.
// ---------------------------------------------------------------------------
template<int D>
__global__ void k_edge_q(const float* __restrict__ feat,
                         const uint4* __restrict__ fb,
                         const float* __restrict__ norms,
                         const void* __restrict__ eidx,
                         float* __restrict__ agg, int E)
{
    constexpr int U = D / 64;       // uint4 per lane per endpoint
    constexpr int NSTRIDE = D / 8;  // uint4 per node row
    long long wid = (long long)((blockIdx.x * (unsigned)blockDim.x + threadIdx.x) >> 5);
    if (wid * 4 >= E) return;
    int lane = threadIdx.x & 31;
    int sl = lane & 7;
    long long e = wid * 4 + (lane >> 3);
    bool valid = (e < E);
    long long ec = valid ? e : (long long)E - 1;

    int s, d;
    if (g_is64) {
        const long long* p = (const long long*)eidx;
        s = (int)p[ec];
        d = (int)p[ec + E];
    } else {
        const int* p = (const int*)eidx;
        s = p[ec];
        d = p[ec + E];
    }
    float nn = norms[s] * norms[d];

    const uint4* ps = fb + (size_t)s * NSTRIDE;
    const uint4* pd = fb + (size_t)d * NSTRIDE;

    uint4 a[U], b[U];
#pragma unroll
    for (int i = 0; i < U; i++) {
        a[i] = ps[sl + 8 * i];
        b[i] = pd[sl + 8 * i];
    }

    float t = 0.f;
    __nv_bfloat162 z2 = __float2bfloat162_rn(0.f);
#pragma unroll
    for (int i = 0; i < U; i++) {
        __nv_bfloat162 acc = z2;
        const __nv_bfloat162* pa = (const __nv_bfloat162*)&a[i];
        const __nv_bfloat162* pb = (const __nv_bfloat162*)&b[i];
#pragma unroll
        for (int j = 0; j < 4; j++) acc = __hfma2(pa[j], pb[j], acc);
        float2 f = __bfloat1622float2(acc);
        t += f.x + f.y;
    }
    // 3-level butterfly within each 8-lane group (warp converged here)
#pragma unroll
    for (int o = 1; o < 8; o <<= 1) t += __shfl_xor_sync(0xffffffffu, t, o);

    float thr = 0.5f * fmaxf(nn, EPSF);
    float margin = BF16_MARGIN * nn;
    bool pass;
    if (fabsf(t - thr) > margin) {
        pass = (t > thr);
    } else {
        // rescue: exact fp32 dot within this 8-lane group (rare; group-uniform branch)
        unsigned hm = 0xFFu << (lane & 24);
        const float4* fs = (const float4*)(feat + (size_t)s * D);
        const float4* fd = (const float4*)(feat + (size_t)d * D);
        float ex = 0.f;
#pragma unroll
        for (int i = 0; i < D / 32; i++) {
            float4 av = fs[sl + 8 * i];
            float4 bv = fd[sl + 8 * i];
            ex += av.x * bv.x + av.y * bv.y + av.z * bv.z + av.w * bv.w;
        }
#pragma unroll
        for (int o = 1; o < 8; o <<= 1) ex += __shfl_xor_sync(hm, ex, o);
        pass = (ex > thr);
    }

    if (valid && pass) {
        // scatter exact fp32 source features (rare)
        const float4* fs = (const float4*)(feat + (size_t)s * D);
        float* out = agg + (size_t)d * D;
#pragma unroll
        for (int i = 0; i < D / 32; i++) {
            float4 av = fs[sl + 8 * i];
            asm volatile("red.global.add.v4.f32 [%0], {%1,%2,%3,%4};" ::
                         "l"(out + (sl + 8 * i) * 4),
                         "f"(av.x), "f"(av.y), "f"(av.z), "f"(av.w)
                         : "memory");
        }
    }
}

// ---------------------------------------------------------------------------
// GEMM1 (f32x2): h = relu(agg1 @ W1^T + b1). Block 64x256, K=128, 256 thr.
// Each warp (ty) owns 8 full rows -> fused epilogue: h, hb, hnorm, agg2 init.
// ---------------------------------------------------------------------------
__global__ __launch_bounds__(256)
void k_gemm1_f2(const float* __restrict__ A, const float* __restrict__ W,
                const float* __restrict__ bias,
                float* __restrict__ hq, uint4* __restrict__ hbq,
                float* __restrict__ hnq, float* __restrict__ aggq, int M)
{
    __shared__ float As[16][64];
    __shared__ float Ws[16][256];
    int tid = threadIdx.x;
    int tx = tid & 31;          // 32 col-chunks of 8
    int ty = tid >> 5;          // 8 row-groups of 8 (= warp id)
    int m0 = blockIdx.x * 64;

    u64 acc[8][4];
#pragma unroll
    for (int i = 0; i < 8; i++)
#pragma unroll
        for (int j = 0; j < 4; j++) acc[i][j] = 0ull;

    for (int k0 = 0; k0 < 128; k0 += 16) {
        {
            int m = tid >> 2, kq = tid & 3;
            int gm = m0 + m;
            if (gm >= M) gm = M - 1;
            float4 v = *(const float4*)(A + (size_t)gm * 128 + k0 + kq * 4);
            As[kq * 4 + 0][m] = v.x;
            As[kq * 4 + 1][m] = v.y;
            As[kq * 4 + 2][m] = v.z;
            As[kq * 4 + 3][m] = v.w;
        }
#pragma unroll
        for (int i = tid; i < 1024; i += 256) {
            int n = i >> 2, kq = i & 3;
            float4 v = *(const float4*)(W + (size_t)n * 128 + k0 + kq * 4);
            Ws[kq * 4 + 0][n] = v.x;
            Ws[kq * 4 + 1][n] = v.y;
            Ws[kq * 4 + 2][n] = v.z;
            Ws[kq * 4 + 3][n] = v.w;
        }
        __syncthreads();
#pragma unroll
        for (int k = 0; k < 16; k++) {
            u64 rm2[8], rn[4];
#pragma unroll
            for (int i = 0; i < 8; i++) rm2[i] = dup2(As[k][ty * 8 + i]);
#pragma unroll
            for (int j = 0; j < 4; j++) rn[j] = *(const u64*)&Ws[k][tx * 8 + 2 * j];
#pragma unroll
            for (int i = 0; i < 8; i++)
#pragma unroll
                for (int j = 0; j < 4; j++)
                    acc[i][j] = fma2(rm2[i], rn[j], acc[i][j]);
        }
        __syncthreads();
    }

    float4 b0 = *(const float4*)&bias[tx * 8];
    float4 b1 = *(const float4*)&bias[tx * 8 + 4];
    float bb[8] = {b0.x, b0.y, b0.z, b0.w, b1.x, b1.y, b1.z, b1.w};

#pragma unroll
    for (int i = 0; i < 8; i++) {
        int gm = m0 + ty * 8 + i;
        float v[8];
#pragma unroll
        for (int j = 0; j < 4; j++) {
            float2 t = unpk(acc[i][j]);
            v[2 * j] = t.x;
            v[2 * j + 1] = t.y;
        }
        float n2 = 0.f;
#pragma unroll
        for (int c = 0; c < 8; c++) {
            v[c] = fmaxf(v[c] + bb[c], 0.f);
            n2 += v[c] * v[c];
        }
#pragma unroll
        for (int o = 16; o; o >>= 1) n2 += __shfl_xor_sync(0xffffffffu, n2, o);
        bool pass = n2 > 0.5f * fmaxf(n2, EPSF);
        if (gm < M) {
            if (tx == 0) hnq[gm] = sqrtf(n2);
            float4 t0 = make_float4(v[0], v[1], v[2], v[3]);
            float4 t1 = make_float4(v[4], v[5], v[6], v[7]);
            float4* hp = (float4*)(hq + (size_t)gm * 256 + tx * 8);
            hp[0] = t0;
            hp[1] = t1;
            float4 z4 = make_float4(0.f, 0.f, 0.f, 0.f);
            float4* ap = (float4*)(aggq + (size_t)gm * 256 + tx * 8);
            ap[0] = pass ? t0 : z4;
            ap[1] = pass ? t1 : z4;
            hbq[(size_t)gm * 32 + tx] =
                make_uint4(pack2bf(v[0], v[1]), pack2bf(v[2], v[3]),
                           pack2bf(v[4], v[5]), pack2bf(v[6], v[7]));
        }
    }
}

// ---------------------------------------------------------------------------
// GEMM2 (f32x2): out = log_softmax(agg2 @ W2^T + b2). Block 128x64, K=256.
// ---------------------------------------------------------------------------
__global__ __launch_bounds__(256)
void k_gemm2_f2(const float* __restrict__ A, const float* __restrict__ W,
                const float* __restrict__ bias,
                float* __restrict__ outq, int M)
{
    __shared__ float As[16][128];
    __shared__ float Ws[16][64];
    int tid = threadIdx.x;
    int tx = tid & 15;
    int ty = tid >> 4;
    int m0 = blockIdx.x * 128;

    u64 acc[8][2];
#pragma unroll
    for (int i = 0; i < 8; i++) {
        acc[i][0] = 0ull;
        acc[i][1] = 0ull;
    }

    for (int k0 = 0; k0 < 256; k0 += 16) {
#pragma unroll
        for (int i = tid; i < 512; i += 256) {
            int m = i >> 2, kq = i & 3;
            int gm = m0 + m;
            if (gm >= M) gm = M - 1;
            float4 v = *(const float4*)(A + (size_t)gm * 256 + k0 + kq * 4);
            As[kq * 4 + 0][m] = v.x;
            As[kq * 4 + 1][m] = v.y;
            As[kq * 4 + 2][m] = v.z;
            As[kq * 4 + 3][m] = v.w;
        }
        {
            int n = tid >> 2, kq = tid & 3;
            float4 v = *(const float4*)(W + (size_t)n * 256 + k0 + kq * 4);
            Ws[kq * 4 + 0][n] = v.x;
            Ws[kq * 4 + 1][n] = v.y;
            Ws[kq * 4 + 2][n] = v.z;
            Ws[kq * 4 + 3][n] = v.w;
        }
        __syncthreads();
#pragma unroll
        for (int k = 0; k < 16; k++) {
            u64 rm2[8], rn[2];
#pragma unroll
            for (int i = 0; i < 8; i++) rm2[i] = dup2(As[k][ty * 8 + i]);
            rn[0] = *(const u64*)&Ws[k][tx * 4];
            rn[1] = *(const u64*)&Ws[k][tx * 4 + 2];
#pragma unroll
            for (int i = 0; i < 8; i++) {
                acc[i][0] = fma2(rm2[i], rn[0], acc[i][0]);
                acc[i][1] = fma2(rm2[i], rn[1], acc[i][1]);
            }
        }
        __syncthreads();
    }

    float4 bv = *(const float4*)&bias[tx * 4];
    float bb[4] = {bv.x, bv.y, bv.z, bv.w};

#pragma unroll
    for (int i = 0; i < 8; i++) {
        int gm = m0 + ty * 8 + i;
        float v[4];
        float2 t0 = unpk(acc[i][0]);
        float2 t1 = unpk(acc[i][1]);
        v[0] = t0.x + bb[0];
        v[1] = t0.y + bb[1];
        v[2] = t1.x + bb[2];
        v[3] = t1.y + bb[3];
        float mx = fmaxf(fmaxf(v[0], v[1]), fmaxf(v[2], v[3]));
#pragma unroll
        for (int o = 1; o < 16; o <<= 1)
            mx = fmaxf(mx, __shfl_xor_sync(0xffffffffu, mx, o));
        float sm = __expf(v[0] - mx) + __expf(v[1] - mx) +
                   __expf(v[2] - mx) + __expf(v[3] - mx);
#pragma unroll
        for (int o = 1; o < 16; o <<= 1)
            sm += __shfl_xor_sync(0xffffffffu, sm, o);
        float l = mx + __logf(sm);
        if (gm < M) {
            *(float4*)(outq + (size_t)gm * 64 + tx * 4) =
                make_float4(v[0] - l, v[1] - l, v[2] - l, v[3] - l);
        }
    }
}

// ---------------------------------------------------------------------------
extern "C" void kernel_launch(void* const* d_in, const int* in_sizes, int n_in,
                              void* d_out, int out_size)
{
    const float* x   = (const float*)d_in[0];
    const void*  eix = d_in[1];
    const float* W1  = (const float*)d_in[2];
    const float* b1  = (const float*)d_in[3];
    const float* W2  = (const float*)d_in[4];
    const float* b2  = (const float*)d_in[5];
    float* out = (float*)d_out;

    int N = in_sizes[0] / D1;      // 50000
    int E = in_sizes[1] / 2;       // 800000
    (void)n_in; (void)out_size;

    float *agg1, *h, *agg2, *xn, *hn;
    uint4 *xb, *hb;
    cudaGetSymbolAddress((void**)&agg1, g_agg1_);
    cudaGetSymbolAddress((void**)&h,    g_h_);
    cudaGetSymbolAddress((void**)&agg2, g_agg2_);
    cudaGetSymbolAddress((void**)&xb,   g_xb_);
    cudaGetSymbolAddress((void**)&hb,   g_hb_);
    cudaGetSymbolAddress((void**)&xn,   g_xnorm);
    cudaGetSymbolAddress((void**)&hn,   g_hnorm);

    k_init_flag<<<1, 1>>>();
    k_detect64<<<(E + 255) / 256, 256>>>(eix, E, N);

    int nodeBlocks = (N * 32 + 255) / 256;
    long long warps4 = ((long long)E + 3) / 4;
    int edgeBlocks = (int)((warps4 * 32 + 255) / 256);

    // ---- Layer 1 ----
    k_norms_init<D1><<<nodeBlocks, 256>>>(x, xn, agg1, (uint2*)xb, N);
    k_edge_q<D1><<<edgeBlocks, 256>>>(x, xb, xn, eix, agg1, E);
    k_gemm1_f2<<<(N + 63) / 64, 256>>>(agg1, W1, b1, h, hb, hn, agg2, N);

    // ---- Layer 2 ----
    k_edge_q<D2><<<edgeBlocks, 256>>>(h, hb, hn, eix, agg2, E);
    k_gemm2_f2<<<(N + 127) / 128, 256>>>(agg2, W2, b2, out, N);
}

// round 11
// speedup vs baseline: 1.3587x; 1.0662x over previous
#include <cuda_runtime.h>
#include <cuda_bf16.h>
#include <stdint.h>
#include <math.h>

#define EPSF 1e-8f
#define NMAX 50000
#define D1 128
#define D2 256
#define BF16_MARGIN 0.02f

typedef unsigned long long u64;

// ---------------------------------------------------------------------------
// Scratch (device globals — no allocation allowed).
// ---------------------------------------------------------------------------
__device__ float4 g_agg1_[(size_t)NMAX * D1 / 4];
__device__ float4 g_h_[(size_t)NMAX * D2 / 4];
__device__ float4 g_agg2_[(size_t)NMAX * D2 / 4];
__device__ uint4  g_xb_[(size_t)NMAX * D1 / 8];
__device__ uint4  g_hb_[(size_t)NMAX * D2 / 8];
__device__ float  g_xnorm[NMAX];
__device__ float  g_hnorm[NMAX];
__device__ int    g_is64;

// ---------------------------------------------------------------------------
// helpers
// ---------------------------------------------------------------------------
__device__ __forceinline__ unsigned pack2bf(float a, float b) {
    __nv_bfloat162 t = __floats2bfloat162_rn(a, b);
    return *(unsigned*)&t;
}
__device__ __forceinline__ uint2 pack_bf16x4(float4 v) {
    uint2 r;
    r.x = pack2bf(v.x, v.y);
    r.y = pack2bf(v.z, v.w);
    return r;
}
// packed f32x2 FMA (B300 FFMA2)
__device__ __forceinline__ u64 dup2(float a) {
    u64 r;
    asm("mov.b64 %0, {%1, %1};" : "=l"(r) : "f"(a));
    return r;
}
__device__ __forceinline__ u64 fma2(u64 a, u64 b, u64 c) {
    u64 d;
    asm("fma.rn.f32x2 %0, %1, %2, %3;" : "=l"(d) : "l"(a), "l"(b), "l"(c));
    return d;
}
__device__ __forceinline__ float2 unpk(u64 a) {
    float2 f;
    asm("mov.b64 {%0, %1}, %2;" : "=f"(f.x), "=f"(f.y) : "l"(a));
    return f;
}

// ---------------------------------------------------------------------------
// small setup kernels
// ---------------------------------------------------------------------------
__global__ void k_init_flag() { g_is64 = 1; }

__global__ void k_detect64(const void* __restrict__ eidx, int E, int N) {
    int i = blockIdx.x * blockDim.x + threadIdx.x;
    if (i < E) {
        long long v = ((const long long*)eidx)[i];
        if (v < 0 || v >= (long long)N) g_is64 = 0;
    }
}

// ---------------------------------------------------------------------------
// Per-node norms + self-loop init + bf16 conversion (layer-1 input x).
// ---------------------------------------------------------------------------
template<int D>
__global__ void k_norms_init(const float* __restrict__ feat,
                             float* __restrict__ norms,
                             float* __restrict__ agg,
                             uint2* __restrict__ fb, int N)
{
    int node = (blockIdx.x * blockDim.x + threadIdx.x) >> 5;
    int lane = threadIdx.x & 31;
    if (node >= N) return;
    const float4* f = (const float4*)(feat + (size_t)node * D);
    float4* a = (float4*)(agg + (size_t)node * D);
    uint2* fbr = fb + (size_t)node * (D / 4);
    float4 v[D / 128];
    float n2 = 0.f;
#pragma unroll
    for (int i = 0; i < D / 128; i++) {
        v[i] = f[lane + 32 * i];
        n2 += v[i].x * v[i].x + v[i].y * v[i].y + v[i].z * v[i].z + v[i].w * v[i].w;
    }
#pragma unroll
    for (int i = 0; i < D / 128; i++) fbr[lane + 32 * i] = pack_bf16x4(v[i]);
#pragma unroll
    for (int o = 16; o; o >>= 1) n2 += __shfl_xor_sync(0xffffffffu, n2, o);
    float nrm = sqrtf(n2);
    if (lane == 0) norms[node] = nrm;
    float denom = fmaxf(nrm * nrm, EPSF);
    bool pass = n2 > 0.5f * denom;
    float4 z = make_float4(0.f, 0.f, 0.f, 0.f);
#pragma unroll
    for (int i = 0; i < D / 128; i++) a[lane + 32 * i] = pass ? v[i] : z;
}

// ---------------------------------------------------------------------------
// Edge pass, quarter-warp per edge (8 lanes/edge, 4 edges/warp).
// Dot computed in chunks of 2+2 uint4 to cap live registers (D=256 case).
// ---------------------------------------------------------------------------
template<int D>
__global__ void k_edge_q(const float* __restrict__ feat,
                         const uint4* __restrict__ fb,
                         const float* __restrict__ norms,
                         const void* __restrict__ eidx,
                         float* __restrict__ agg, int E)
{
    constexpr int NSTRIDE = D / 8;   // uint4 per node row
    constexpr int NCHUNK = D / 128;  // 128 bf16 dims per chunk
    long long wid = (long long)((blockIdx.x * (unsigned)blockDim.x + threadIdx.x) >> 5);
    if (wid * 4 >= E) return;
    int lane = threadIdx.x & 31;
    int sl = lane & 7;
    long long e = wid * 4 + (lane >> 3);
    bool valid = (e < E);
    long long ec = valid ? e : (long long)E - 1;

    int s, d;
    if (g_is64) {
        const long long* p = (const long long*)eidx;
        s = (int)p[ec];
        d = (int)p[ec + E];
    } else {
        const int* p = (const int*)eidx;
        s = p[ec];
        d = p[ec + E];
    }
    float nn = norms[s] * norms[d];

    const uint4* ps = fb + (size_t)s * NSTRIDE;
    const uint4* pd = fb + (size_t)d * NSTRIDE;

    float t = 0.f;
    __nv_bfloat162 z2 = __float2bfloat162_rn(0.f);
#pragma unroll
    for (int ch = 0; ch < NCHUNK; ch++) {
        uint4 a0 = ps[sl + 16 * ch];
        uint4 a1 = ps[sl + 16 * ch + 8];
        uint4 b0 = pd[sl + 16 * ch];
        uint4 b1 = pd[sl + 16 * ch + 8];
        __nv_bfloat162 acc0 = z2, acc1 = z2;
        const __nv_bfloat162* pa0 = (const __nv_bfloat162*)&a0;
        const __nv_bfloat162* pb0 = (const __nv_bfloat162*)&b0;
        const __nv_bfloat162* pa1 = (const __nv_bfloat162*)&a1;
        const __nv_bfloat162* pb1 = (const __nv_bfloat162*)&b1;
#pragma unroll
        for (int j = 0; j < 4; j++) {
            acc0 = __hfma2(pa0[j], pb0[j], acc0);
            acc1 = __hfma2(pa1[j], pb1[j], acc1);
        }
        float2 f0 = __bfloat1622float2(acc0);
        float2 f1 = __bfloat1622float2(acc1);
        t += f0.x + f0.y + f1.x + f1.y;
    }
    // 3-level butterfly within each 8-lane group (warp converged here)
#pragma unroll
    for (int o = 1; o < 8; o <<= 1) t += __shfl_xor_sync(0xffffffffu, t, o);

    float thr = 0.5f * fmaxf(nn, EPSF);
    float margin = BF16_MARGIN * nn;
    bool pass;
    if (fabsf(t - thr) > margin) {
        pass = (t > thr);
    } else {
        // rescue: exact fp32 dot within this 8-lane group (rare; group-uniform)
        unsigned hm = 0xFFu << (lane & 24);
        const float4* fs = (const float4*)(feat + (size_t)s * D);
        const float4* fd = (const float4*)(feat + (size_t)d * D);
        float ex = 0.f;
#pragma unroll
        for (int i = 0; i < D / 32; i++) {
            float4 av = fs[sl + 8 * i];
            float4 bv = fd[sl + 8 * i];
            ex += av.x * bv.x + av.y * bv.y + av.z * bv.z + av.w * bv.w;
        }
#pragma unroll
        for (int o = 1; o < 8; o <<= 1) ex += __shfl_xor_sync(hm, ex, o);
        pass = (ex > thr);
    }

    if (valid && pass) {
        const float4* fs = (const float4*)(feat + (size_t)s * D);
        float* out = agg + (size_t)d * D;
#pragma unroll
        for (int i = 0; i < D / 32; i++) {
            float4 av = fs[sl + 8 * i];
            asm volatile("red.global.add.v4.f32 [%0], {%1,%2,%3,%4};" ::
                         "l"(out + (sl + 8 * i) * 4),
                         "f"(av.x), "f"(av.y), "f"(av.z), "f"(av.w)
                         : "memory");
        }
    }
}

// ---------------------------------------------------------------------------
// GEMM1 (f32x2): h = relu(agg1 @ W1^T + b1). Block 64x256, K=128, 256 thr.
// Conflict-free cols: lane tx owns cols {2tx, 2tx+1} + 64*j, j=0..3.
// Fused epilogue: h, hb (bf16), hnorm, agg2 init.
// ---------------------------------------------------------------------------
__global__ __launch_bounds__(256)
void k_gemm1_f2(const float* __restrict__ A, const float* __restrict__ W,
                const float* __restrict__ bias,
                float* __restrict__ hq, unsigned* __restrict__ hbq,
                float* __restrict__ hnq, float* __restrict__ aggq, int M)
{
    __shared__ float As[16][64];
    __shared__ float Ws[16][256];
    int tid = threadIdx.x;
    int tx = tid & 31;          // lane: col pair owner
    int ty = tid >> 5;          // warp: 8-row group
    int m0 = blockIdx.x * 64;

    u64 acc[8][4];
#pragma unroll
    for (int i = 0; i < 8; i++)
#pragma unroll
        for (int j = 0; j < 4; j++) acc[i][j] = 0ull;

    for (int k0 = 0; k0 < 128; k0 += 16) {
        {
            int m = tid >> 2, kq = tid & 3;
            int gm = m0 + m;
            if (gm >= M) gm = M - 1;
            float4 v = *(const float4*)(A + (size_t)gm * 128 + k0 + kq * 4);
            As[kq * 4 + 0][m] = v.x;
            As[kq * 4 + 1][m] = v.y;
            As[kq * 4 + 2][m] = v.z;
            As[kq * 4 + 3][m] = v.w;
        }
#pragma unroll
        for (int i = tid; i < 1024; i += 256) {
            int n = i >> 2, kq = i & 3;
            float4 v = *(const float4*)(W + (size_t)n * 128 + k0 + kq * 4);
            Ws[kq * 4 + 0][n] = v.x;
            Ws[kq * 4 + 1][n] = v.y;
            Ws[kq * 4 + 2][n] = v.z;
            Ws[kq * 4 + 3][n] = v.w;
        }
        __syncthreads();
#pragma unroll
        for (int k = 0; k < 16; k++) {
            u64 rm2[8], rn[4];
#pragma unroll
            for (int i = 0; i < 8; i++) rm2[i] = dup2(As[k][ty * 8 + i]);
#pragma unroll
            for (int j = 0; j < 4; j++)
                rn[j] = *(const u64*)&Ws[k][2 * tx + 64 * j];
#pragma unroll
            for (int i = 0; i < 8; i++)
#pragma unroll
                for (int j = 0; j < 4; j++)
                    acc[i][j] = fma2(rm2[i], rn[j], acc[i][j]);
        }
        __syncthreads();
    }

    float2 bb[4];
#pragma unroll
    for (int j = 0; j < 4; j++) bb[j] = *(const float2*)&bias[2 * tx + 64 * j];

#pragma unroll
    for (int i = 0; i < 8; i++) {
        int gm = m0 + ty * 8 + i;
        float v[8];
        float n2 = 0.f;
#pragma unroll
        for (int j = 0; j < 4; j++) {
            float2 t = unpk(acc[i][j]);
            float v0 = fmaxf(t.x + bb[j].x, 0.f);
            float v1 = fmaxf(t.y + bb[j].y, 0.f);
            v[2 * j] = v0;
            v[2 * j + 1] = v1;
            n2 += v0 * v0 + v1 * v1;
        }
#pragma unroll
        for (int o = 16; o; o >>= 1) n2 += __shfl_xor_sync(0xffffffffu, n2, o);
        bool pass = n2 > 0.5f * fmaxf(n2, EPSF);
        if (gm < M) {
            if (tx == 0) hnq[gm] = sqrtf(n2);
            float2 z2 = make_float2(0.f, 0.f);
#pragma unroll
            for (int j = 0; j < 4; j++) {
                float2 hv = make_float2(v[2 * j], v[2 * j + 1]);
                *(float2*)(hq + (size_t)gm * 256 + 2 * tx + 64 * j) = hv;
                *(float2*)(aggq + (size_t)gm * 256 + 2 * tx + 64 * j) = pass ? hv : z2;
                hbq[(size_t)gm * 128 + tx + 32 * j] = pack2bf(hv.x, hv.y);
            }
        }
    }
}

// ---------------------------------------------------------------------------
// GEMM2 (f32x2): out = log_softmax(agg2 @ W2^T + b2). Block 128x64, K=256.
// Conflict-free cols: lane tx (0..15) owns cols {2tx, 2tx+1} + 32*j, j=0..1.
// ---------------------------------------------------------------------------
__global__ __launch_bounds__(256)
void k_gemm2_f2(const float* __restrict__ A, const float* __restrict__ W,
                const float* __restrict__ bias,
                float* __restrict__ outq, int M)
{
    __shared__ float As[16][128];
    __shared__ float Ws[16][64];
    int tid = threadIdx.x;
    int tx = tid & 15;
    int ty = tid >> 4;
    int m0 = blockIdx.x * 128;

    u64 acc[8][2];
#pragma unroll
    for (int i = 0; i < 8; i++) {
        acc[i][0] = 0ull;
        acc[i][1] = 0ull;
    }

    for (int k0 = 0; k0 < 256; k0 += 16) {
#pragma unroll
        for (int i = tid; i < 512; i += 256) {
            int m = i >> 2, kq = i & 3;
            int gm = m0 + m;
            if (gm >= M) gm = M - 1;
            float4 v = *(const float4*)(A + (size_t)gm * 256 + k0 + kq * 4);
            As[kq * 4 + 0][m] = v.x;
            As[kq * 4 + 1][m] = v.y;
            As[kq * 4 + 2][m] = v.z;
            As[kq * 4 + 3][m] = v.w;
        }
        {
            int n = tid >> 2, kq = tid & 3;
            float4 v = *(const float4*)(W + (size_t)n * 256 + k0 + kq * 4);
            Ws[kq * 4 + 0][n] = v.x;
            Ws[kq * 4 + 1][n] = v.y;
            Ws[kq * 4 + 2][n] = v.z;
            Ws[kq * 4 + 3][n] = v.w;
        }
        __syncthreads();
#pragma unroll
        for (int k = 0; k < 16; k++) {
            u64 rm2[8], rn[2];
#pragma unroll
            for (int i = 0; i < 8; i++) rm2[i] = dup2(As[k][ty * 8 + i]);
            rn[0] = *(const u64*)&Ws[k][2 * tx];
            rn[1] = *(const u64*)&Ws[k][2 * tx + 32];
#pragma unroll
            for (int i = 0; i < 8; i++) {
                acc[i][0] = fma2(rm2[i], rn[0], acc[i][0]);
                acc[i][1] = fma2(rm2[i], rn[1], acc[i][1]);
            }
        }
        __syncthreads();
    }

    float2 bb0 = *(const float2*)&bias[2 * tx];
    float2 bb1 = *(const float2*)&bias[2 * tx + 32];

#pragma unroll
    for (int i = 0; i < 8; i++) {
        int gm = m0 + ty * 8 + i;
        float2 t0 = unpk(acc[i][0]);
        float2 t1 = unpk(acc[i][1]);
        float v0 = t0.x + bb0.x, v1 = t0.y + bb0.y;
        float v2 = t1.x + bb1.x, v3 = t1.y + bb1.y;
        // log_softmax over the 16 lanes holding this row's 64 cols
        float mx = fmaxf(fmaxf(v0, v1), fmaxf(v2, v3));
#pragma unroll
        for (int o = 1; o < 16; o <<= 1)
            mx = fmaxf(mx, __shfl_xor_sync(0xffffffffu, mx, o));
        float sm = __expf(v0 - mx) + __expf(v1 - mx) +
                   __expf(v2 - mx) + __expf(v3 - mx);
#pragma unroll
        for (int o = 1; o < 16; o <<= 1)
            sm += __shfl_xor_sync(0xffffffffu, sm, o);
        float l = mx + __logf(sm);
        if (gm < M) {
            *(float2*)(outq + (size_t)gm * 64 + 2 * tx) = make_float2(v0 - l, v1 - l);
            *(float2*)(outq + (size_t)gm * 64 + 2 * tx + 32) = make_float2(v2 - l, v3 - l);
        }
    }
}

// ---------------------------------------------------------------------------
extern "C" void kernel_launch(void* const* d_in, const int* in_sizes, int n_in,
                              void* d_out, int out_size)
{
    const float* x   = (const float*)d_in[0];
    const void*  eix = d_in[1];
    const float* W1  = (const float*)d_in[2];
    const float* b1  = (const float*)d_in[3];
    const float* W2  = (const float*)d_in[4];
    const float* b2  = (const float*)d_in[5];
    float* out = (float*)d_out;

    int N = in_sizes[0] / D1;      // 50000
    int E = in_sizes[1] / 2;       // 800000
    (void)n_in; (void)out_size;

    float *agg1, *h, *agg2, *xn, *hn;
    uint4 *xb, *hb;
    cudaGetSymbolAddress((void**)&agg1, g_agg1_);
    cudaGetSymbolAddress((void**)&h,    g_h_);
    cudaGetSymbolAddress((void**)&agg2, g_agg2_);
    cudaGetSymbolAddress((void**)&xb,   g_xb_);
    cudaGetSymbolAddress((void**)&hb,   g_hb_);
    cudaGetSymbolAddress((void**)&xn,   g_xnorm);
    cudaGetSymbolAddress((void**)&hn,   g_hnorm);

    k_init_flag<<<1, 1>>>();
    k_detect64<<<(E + 255) / 256, 256>>>(eix, E, N);

    int nodeBlocks = (N * 32 + 255) / 256;
    long long warps4 = ((long long)E + 3) / 4;
    int edgeBlocks = (int)((warps4 * 32 + 255) / 256);

    // ---- Layer 1 ----
    k_norms_init<D1><<<nodeBlocks, 256>>>(x, xn, agg1, (uint2*)xb, N);
    k_edge_q<D1><<<edgeBlocks, 256>>>(x, xb, xn, eix, agg1, E);
    k_gemm1_f2<<<(N + 63) / 64, 256>>>(agg1, W1, b1, h, (unsigned*)hb, hn, agg2, N);

    // ---- Layer 2 ----
    k_edge_q<D2><<<edgeBlocks, 256>>>(h, hb, hn, eix, agg2, E);
    k_gemm2_f2<<<(N + 127) / 128, 256>>>(agg2, W2, b2, out, N);
}